// round 16
// baseline (speedup 1.0000x reference)
#include <cuda_runtime.h>
#include <cuda_bf16.h>
#include <stdint.h>
#include <math.h>

#define Bq 512
#define Tq 512
#define Fq 52
#define Eq 64
#define Hq 128
#define G4q 512
#define NROWS (Bq*Tq)

// Scratch (device globals; no dynamic allocation allowed)
__device__ __nv_bfloat16 g_henc_h[NROWS * Eq];   // 32 MB  h_enc hi
__device__ __nv_bfloat16 g_henc_l[NROWS * Eq];   // 32 MB  h_enc lo
__device__ __nv_bfloat16 g_wih_h[G4q * Eq];      // W_ih hi
__device__ __nv_bfloat16 g_wih_l[G4q * Eq];      // W_ih lo
__device__ __nv_bfloat16 g_w1h[128 * 64];        // W1 hi (K padded to 64)
__device__ __nv_bfloat16 g_w1l[128 * 64];        // W1 lo
__device__ __nv_bfloat16 g_w2h[64 * 128];        // W2 hi
__device__ __nv_bfloat16 g_w2l[64 * 128];        // W2 lo
__device__ float g_bias[G4q];                    // b_ih + b_hh
__device__ float g_gx[NROWS * G4q];              // 512 MB [t][b][512]
__device__ float g_hfin[Bq * Hq];                // final hidden state

// ---------------------------------------------------------------------------
// helpers
// ---------------------------------------------------------------------------
__device__ __forceinline__ unsigned smem_u32(const void* p) {
    unsigned a;
    asm("{ .reg .u64 t; cvta.to.shared.u64 t, %1; cvt.u32.u64 %0, t; }"
        : "=r"(a) : "l"(p));
    return a;
}

// HW tanh (MUFU.TANH, sm_75+); sigmoid via tanh identity
__device__ __forceinline__ float tanh_hw(float x) {
    float r;
    asm("tanh.approx.f32 %0, %1;" : "=f"(r) : "f"(x));
    return r;
}
__device__ __forceinline__ float sig_hw(float x) {
    return fmaf(tanh_hw(0.5f * x), 0.5f, 0.5f);
}

// pack two bf16 (e0 -> low half, e1 -> high half)
__device__ __forceinline__ unsigned pack_bf16(__nv_bfloat16 e0, __nv_bfloat16 e1) {
    return ((unsigned)__bfloat16_as_ushort(e1) << 16) |
           (unsigned)__bfloat16_as_ushort(e0);
}

// m16n8k16 row.col f32.bf16.bf16.f32 (baseline PTX, sm_80+)
__device__ __forceinline__ void mma_bf16(float c[4], const unsigned a[4],
                                         unsigned b0, unsigned b1) {
    asm volatile(
        "mma.sync.aligned.m16n8k16.row.col.f32.bf16.bf16.f32 "
        "{%0,%1,%2,%3}, {%4,%5,%6,%7}, {%8,%9}, {%0,%1,%2,%3};"
        : "+f"(c[0]), "+f"(c[1]), "+f"(c[2]), "+f"(c[3])
        : "r"(a[0]), "r"(a[1]), "r"(a[2]), "r"(a[3]), "r"(b0), "r"(b1));
}

// ldmatrix wrappers (baseline PTX, sm_75+)
__device__ __forceinline__ void ldsm_x4(unsigned r[4], unsigned addr) {
    asm volatile("ldmatrix.sync.aligned.m8n8.x4.shared.b16 {%0,%1,%2,%3}, [%4];"
        : "=r"(r[0]), "=r"(r[1]), "=r"(r[2]), "=r"(r[3]) : "r"(addr));
}
__device__ __forceinline__ void ldsm_x2(unsigned& r0, unsigned& r1, unsigned addr) {
    asm volatile("ldmatrix.sync.aligned.m8n8.x2.shared.b16 {%0,%1}, [%2];"
        : "=r"(r0), "=r"(r1) : "r"(addr));
}

// ---------------------------------------------------------------------------
// prep: split W_ih / W1 / W2 to bf16 hi/lo; bias = b_ih + b_hh
// ---------------------------------------------------------------------------
__global__ void prep_kernel(const float* __restrict__ Wih,
                            const float* __restrict__ bih,
                            const float* __restrict__ bhh,
                            const float* __restrict__ W1,
                            const float* __restrict__ W2)
{
    int i = blockIdx.x * 256 + threadIdx.x;
    if (i < G4q * Eq) {
        float v = Wih[i];
        __nv_bfloat16 h = __float2bfloat16(v);
        g_wih_h[i] = h;
        g_wih_l[i] = __float2bfloat16(v - __bfloat162float(h));
    }
    if (i < 128 * 64) {
        int r = i >> 6, k = i & 63;
        float v = (k < Fq) ? W1[r * Fq + k] : 0.f;
        __nv_bfloat16 h = __float2bfloat16(v);
        g_w1h[i] = h;
        g_w1l[i] = __float2bfloat16(v - __bfloat162float(h));
    }
    if (i < 64 * 128) {
        float v = W2[i];
        __nv_bfloat16 h = __float2bfloat16(v);
        g_w2h[i] = h;
        g_w2l[i] = __float2bfloat16(v - __bfloat162float(h));
    }
    if (i < G4q) g_bias[i] = bih[i] + bhh[i];
}

// ---------------------------------------------------------------------------
// Fused HMMA encoder (unchanged from R11)
// ---------------------------------------------------------------------------
#define E_W2H 0
#define E_W2L 17408
#define E_R   34816
#define E_AXH E_R
#define E_AXL (E_R + 9216)
#define E_W1H (E_R + 18432)
#define E_W1L (E_R + 36864)
#define E_H1H E_R
#define E_H1L (E_R + 17408)
#define E_B1  (E_R + 55296)
#define E_B2  (E_B1 + 512)
#define E_TOTAL (E_B2 + 256)

__global__ __launch_bounds__(256) void enc_hmma_kernel(
    const float* __restrict__ x,
    const float* __restrict__ b1, const float* __restrict__ b2)
{
    extern __shared__ char smc[];
    __nv_bfloat16* W2h = (__nv_bfloat16*)(smc + E_W2H);
    __nv_bfloat16* W2l = (__nv_bfloat16*)(smc + E_W2L);
    __nv_bfloat16* Axh = (__nv_bfloat16*)(smc + E_AXH);
    __nv_bfloat16* Axl = (__nv_bfloat16*)(smc + E_AXL);
    __nv_bfloat16* W1h = (__nv_bfloat16*)(smc + E_W1H);
    __nv_bfloat16* W1l = (__nv_bfloat16*)(smc + E_W1L);
    __nv_bfloat16* H1h = (__nv_bfloat16*)(smc + E_H1H);
    __nv_bfloat16* H1l = (__nv_bfloat16*)(smc + E_H1L);
    float* b1s = (float*)(smc + E_B1);
    float* b2s = (float*)(smc + E_B2);

    const int tid  = threadIdx.x;
    const int w    = tid >> 5;
    const int lane = tid & 31;
    const int qr   = lane >> 2;
    const int qc   = (lane & 3) * 2;
    const int row0 = blockIdx.x * 64;

    for (int idx = tid; idx < 64 * 32; idx += 256) {
        int r = idx >> 5, c4 = (idx & 31) * 4;
        *(uint2*)&W2h[r * 136 + c4] = *(const uint2*)(g_w2h + r * 128 + c4);
        *(uint2*)&W2l[r * 136 + c4] = *(const uint2*)(g_w2l + r * 128 + c4);
    }
    for (int idx = tid; idx < 128 * 16; idx += 256) {
        int r = idx >> 4, c4 = (idx & 15) * 4;
        *(uint2*)&W1h[r * 72 + c4] = *(const uint2*)(g_w1h + r * 64 + c4);
        *(uint2*)&W1l[r * 72 + c4] = *(const uint2*)(g_w1l + r * 64 + c4);
    }
    for (int idx = tid; idx < 64 * Fq; idx += 256) {
        int r = idx / Fq, k = idx % Fq;
        float v = x[(size_t)(row0 + r) * Fq + k];
        __nv_bfloat16 h = __float2bfloat16(v);
        Axh[r * 72 + k] = h;
        Axl[r * 72 + k] = __float2bfloat16(v - __bfloat162float(h));
    }
    for (int idx = tid; idx < 64 * 12; idx += 256) {
        int r = idx / 12, k = Fq + idx % 12;
        Axh[r * 72 + k] = __float2bfloat16(0.f);
        Axl[r * 72 + k] = __float2bfloat16(0.f);
    }
    if (tid < 128) b1s[tid] = b1[tid];
    if (tid < 64)  b2s[tid] = b2[tid];
    __syncthreads();

    // phase 1
    float cH[4][2][4], cX[4][2][4];
    #pragma unroll
    for (int mt = 0; mt < 4; mt++)
        #pragma unroll
        for (int nb = 0; nb < 2; nb++)
            #pragma unroll
            for (int j = 0; j < 4; j++) { cH[mt][nb][j] = 0.f; cX[mt][nb][j] = 0.f; }

    #pragma unroll
    for (int kt = 0; kt < 4; kt++) {
        int bk = kt * 16 + qc;
        unsigned bh[2][2], bl[2][2];
        #pragma unroll
        for (int nb = 0; nb < 2; nb++) {
            int nrow = (w * 2 + nb) * 8 + qr;
            bh[nb][0] = *(const unsigned*)&W1h[nrow * 72 + bk];
            bh[nb][1] = *(const unsigned*)&W1h[nrow * 72 + bk + 8];
            bl[nb][0] = *(const unsigned*)&W1l[nrow * 72 + bk];
            bl[nb][1] = *(const unsigned*)&W1l[nrow * 72 + bk + 8];
        }
        #pragma unroll
        for (int mt = 0; mt < 4; mt++) {
            int ar = mt * 16 + qr;
            unsigned a_h[4] = {
                *(const unsigned*)&Axh[ar * 72 + bk],
                *(const unsigned*)&Axh[(ar + 8) * 72 + bk],
                *(const unsigned*)&Axh[ar * 72 + bk + 8],
                *(const unsigned*)&Axh[(ar + 8) * 72 + bk + 8] };
            unsigned a_l[4] = {
                *(const unsigned*)&Axl[ar * 72 + bk],
                *(const unsigned*)&Axl[(ar + 8) * 72 + bk],
                *(const unsigned*)&Axl[ar * 72 + bk + 8],
                *(const unsigned*)&Axl[(ar + 8) * 72 + bk + 8] };
            #pragma unroll
            for (int nb = 0; nb < 2; nb++) {
                mma_bf16(cH[mt][nb], a_h, bh[nb][0], bh[nb][1]);
                mma_bf16(cX[mt][nb], a_h, bl[nb][0], bl[nb][1]);
                mma_bf16(cX[mt][nb], a_l, bh[nb][0], bh[nb][1]);
            }
        }
    }
    __syncthreads();

    #pragma unroll
    for (int mt = 0; mt < 4; mt++) {
        #pragma unroll
        for (int nb = 0; nb < 2; nb++) {
            int ncol = (w * 2 + nb) * 8 + qc;
            float bv0 = b1s[ncol], bv1 = b1s[ncol + 1];
            #pragma unroll
            for (int half = 0; half < 2; half++) {
                int r = mt * 16 + qr + half * 8;
                float v0 = cH[mt][nb][half*2]   + cX[mt][nb][half*2]   + bv0;
                float v1 = cH[mt][nb][half*2+1] + cX[mt][nb][half*2+1] + bv1;
                v0 = v0 > 0.f ? v0 : 0.f;
                v1 = v1 > 0.f ? v1 : 0.f;
                __nv_bfloat16 h0 = __float2bfloat16(v0);
                __nv_bfloat16 h1 = __float2bfloat16(v1);
                *(unsigned*)&H1h[r * 136 + ncol] = pack_bf16(h0, h1);
                *(unsigned*)&H1l[r * 136 + ncol] = pack_bf16(
                    __float2bfloat16(v0 - __bfloat162float(h0)),
                    __float2bfloat16(v1 - __bfloat162float(h1)));
            }
        }
    }
    __syncthreads();

    // phase 2
    float dH[4][4], dX[4][4];
    #pragma unroll
    for (int mt = 0; mt < 4; mt++)
        #pragma unroll
        for (int j = 0; j < 4; j++) { dH[mt][j] = 0.f; dX[mt][j] = 0.f; }

    #pragma unroll
    for (int kt = 0; kt < 8; kt++) {
        int bk = kt * 16 + qc;
        int nrow = w * 8 + qr;
        unsigned bh0 = *(const unsigned*)&W2h[nrow * 136 + bk];
        unsigned bh1 = *(const unsigned*)&W2h[nrow * 136 + bk + 8];
        unsigned bl0 = *(const unsigned*)&W2l[nrow * 136 + bk];
        unsigned bl1 = *(const unsigned*)&W2l[nrow * 136 + bk + 8];
        #pragma unroll
        for (int mt = 0; mt < 4; mt++) {
            int ar = mt * 16 + qr;
            unsigned a_h[4] = {
                *(const unsigned*)&H1h[ar * 136 + bk],
                *(const unsigned*)&H1h[(ar + 8) * 136 + bk],
                *(const unsigned*)&H1h[ar * 136 + bk + 8],
                *(const unsigned*)&H1h[(ar + 8) * 136 + bk + 8] };
            unsigned a_l[4] = {
                *(const unsigned*)&H1l[ar * 136 + bk],
                *(const unsigned*)&H1l[(ar + 8) * 136 + bk],
                *(const unsigned*)&H1l[ar * 136 + bk + 8],
                *(const unsigned*)&H1l[(ar + 8) * 136 + bk + 8] };
            mma_bf16(dH[mt], a_h, bh0, bh1);
            mma_bf16(dX[mt], a_h, bl0, bl1);
            mma_bf16(dX[mt], a_l, bh0, bh1);
        }
    }

    {
        int ncol = w * 8 + qc;
        float bv0 = b2s[ncol], bv1 = b2s[ncol + 1];
        #pragma unroll
        for (int mt = 0; mt < 4; mt++) {
            #pragma unroll
            for (int half = 0; half < 2; half++) {
                int r = row0 + mt * 16 + qr + half * 8;
                float v0 = dH[mt][half*2]   + dX[mt][half*2]   + bv0;
                float v1 = dH[mt][half*2+1] + dX[mt][half*2+1] + bv1;
                v0 = v0 > 0.f ? v0 : 0.f;
                v1 = v1 > 0.f ? v1 : 0.f;
                __nv_bfloat16 h0 = __float2bfloat16(v0);
                __nv_bfloat16 h1 = __float2bfloat16(v1);
                *(unsigned*)(g_henc_h + (size_t)r * Eq + ncol) = pack_bf16(h0, h1);
                *(unsigned*)(g_henc_l + (size_t)r * Eq + ncol) = pack_bf16(
                    __float2bfloat16(v0 - __bfloat162float(h0)),
                    __float2bfloat16(v1 - __bfloat162float(h1)));
            }
        }
    }
}

// ---------------------------------------------------------------------------
// gx via HMMA bf16 2-way split, fragments loaded with ldmatrix. (R14)
// ---------------------------------------------------------------------------
#define GX_RSTRIDE_B 144

__global__ __launch_bounds__(256) void gx_hmma_kernel()
{
    __shared__ __nv_bfloat16 Ah[64][72], Al[64][72];
    __shared__ __nv_bfloat16 Bh[64][72], Bl[64][72];
    __shared__ float bs[64];

    const int tid  = threadIdx.x;
    const int w    = tid >> 5;
    const int lane = tid & 31;
    const int row0 = blockIdx.x * 64;
    const int cb   = blockIdx.y * 64;

    for (int idx = tid; idx < 64 * 16; idx += 256) {
        int r  = idx >> 4;
        int k4 = (idx & 15) * 4;
        size_t ga = (size_t)(row0 + r) * Eq + k4;
        size_t gb = (size_t)(cb + r) * Eq + k4;
        *(uint2*)&Ah[r][k4] = *(const uint2*)(g_henc_h + ga);
        *(uint2*)&Al[r][k4] = *(const uint2*)(g_henc_l + ga);
        *(uint2*)&Bh[r][k4] = *(const uint2*)(g_wih_h + gb);
        *(uint2*)&Bl[r][k4] = *(const uint2*)(g_wih_l + gb);
    }
    if (tid < 64) bs[tid] = g_bias[cb + tid];
    __syncthreads();

    const int qr = lane >> 2;
    const int qc = (lane & 3) * 2;

    const unsigned a_lane = (unsigned)((((lane >> 3) & 1) * 8 + (lane & 7)) * GX_RSTRIDE_B
                                       + (lane >> 4) * 16);
    const unsigned b_lane = (unsigned)((lane & 7) * GX_RSTRIDE_B + ((lane >> 3) & 1) * 16);

    const unsigned uAh = smem_u32(Ah), uAl = smem_u32(Al);
    const unsigned uBh = smem_u32(Bh) + (unsigned)(w * 8 * GX_RSTRIDE_B);
    const unsigned uBl = smem_u32(Bl) + (unsigned)(w * 8 * GX_RSTRIDE_B);

    float cA[4][4], cB[4][4], cC[4][4];
    #pragma unroll
    for (int m = 0; m < 4; m++)
        #pragma unroll
        for (int j = 0; j < 4; j++) { cA[m][j] = 0.f; cB[m][j] = 0.f; cC[m][j] = 0.f; }

    #pragma unroll
    for (int kt = 0; kt < 4; kt++) {
        unsigned bh0, bh1, bl0, bl1;
        ldsm_x2(bh0, bh1, uBh + b_lane + kt * 32);
        ldsm_x2(bl0, bl1, uBl + b_lane + kt * 32);
        #pragma unroll
        for (int mt = 0; mt < 4; mt++) {
            unsigned a_h[4], a_l[4];
            ldsm_x4(a_h, uAh + (unsigned)(mt * 16 * GX_RSTRIDE_B) + a_lane + kt * 32);
            ldsm_x4(a_l, uAl + (unsigned)(mt * 16 * GX_RSTRIDE_B) + a_lane + kt * 32);
            mma_bf16(cA[mt], a_h, bh0, bh1);
            mma_bf16(cB[mt], a_h, bl0, bl1);
            mma_bf16(cC[mt], a_l, bh0, bh1);
        }
    }

    const int ncol = cb + w*8 + qc;
    const float bv0 = bs[w*8 + qc];
    const float bv1 = bs[w*8 + qc + 1];
    #pragma unroll
    for (int mt = 0; mt < 4; mt++) {
        int r1 = row0 + mt*16 + qr;
        int r2 = r1 + 8;
        int b1i = r1 >> 9, t1 = r1 & 511;
        int b2i = r2 >> 9, t2 = r2 & 511;
        float2 o1 = make_float2(cA[mt][0] + cB[mt][0] + cC[mt][0] + bv0,
                                cA[mt][1] + cB[mt][1] + cC[mt][1] + bv1);
        float2 o2 = make_float2(cA[mt][2] + cB[mt][2] + cC[mt][2] + bv0,
                                cA[mt][3] + cB[mt][3] + cC[mt][3] + bv1);
        *(float2*)(g_gx + ((size_t)t1 * Bq + b1i) * G4q + ncol) = o1;
        *(float2*)(g_gx + ((size_t)t2 * Bq + b2i) * G4q + ncol) = o2;
    }
}

// ---------------------------------------------------------------------------
// Persistent LSTM, CLUSTER-FREE: 128 CTAs x 512 threads, 4 batches per CTA.
// Each CTA owns ALL 512 gate rows; warp w (0..15) owns column j = w*8+qr with
// the gate-remap (m-tile mt: row qr -> gate 2mt, row qr+8 -> gate 2mt+1), so
// D registers carry all 4 gates of j for batches qc, qc+1 (qc<4 valid; B rows
// 4-7 stay zero). Step sync = one __syncthreads. No DSMEM, no cluster barrier.
// ---------------------------------------------------------------------------
#define HB_ROW_BF16 152
#define HB_ROW_B    (HB_ROW_BF16*2)       // 304
#define HB_ARR_B    (8*HB_ROW_B)          // 2432
#define HB_HI(p)    ((p)*2*HB_ARR_B)
#define HB_LO(p)    ((p)*2*HB_ARR_B + HB_ARR_B)
#define L_SMEM_B    (4*HB_ARR_B)

__global__ __launch_bounds__(512, 1)
void lstm_persist_kernel(const float* __restrict__ Whh)
{
    extern __shared__ char smc[];
    const unsigned sbase = smem_u32(smc);

    const int tid  = threadIdx.x;
    const int w    = tid >> 5;        // 0..15
    const int lane = tid & 31;
    const int qr   = lane >> 2;
    const int qc   = (lane & 3) << 1; // 0,2,4,6; valid batches when qc<4
    const int cl   = blockIdx.x;      // batches [cl*4, cl*4+4)
    const int jglob = w * 8 + qr;     // 0..127
    const bool valid = (qc < 4);

    // ---- A fragments: all 4 gates of column jglob ----
    unsigned ahi[2][8][4], alo[2][8][4];
    #pragma unroll
    for (int mt = 0; mt < 2; mt++) {
        long r0 = (long)((mt*2 + 0) * Hq + jglob) * Hq;   // even gate row
        long r1 = (long)((mt*2 + 1) * Hq + jglob) * Hq;   // odd gate row
        #pragma unroll
        for (int kt = 0; kt < 8; kt++) {
            int c0 = kt*16 + qc;
            float w00 = Whh[r0 + c0],     w01 = Whh[r0 + c0 + 1];
            float w08 = Whh[r0 + c0 + 8], w09 = Whh[r0 + c0 + 9];
            float w10 = Whh[r1 + c0],     w11 = Whh[r1 + c0 + 1];
            float w18 = Whh[r1 + c0 + 8], w19 = Whh[r1 + c0 + 9];
            __nv_bfloat16 h00 = __float2bfloat16(w00), h01 = __float2bfloat16(w01);
            __nv_bfloat16 h08 = __float2bfloat16(w08), h09 = __float2bfloat16(w09);
            __nv_bfloat16 h10 = __float2bfloat16(w10), h11 = __float2bfloat16(w11);
            __nv_bfloat16 h18 = __float2bfloat16(w18), h19 = __float2bfloat16(w19);
            ahi[mt][kt][0] = pack_bf16(h00, h01);
            ahi[mt][kt][1] = pack_bf16(h10, h11);
            ahi[mt][kt][2] = pack_bf16(h08, h09);
            ahi[mt][kt][3] = pack_bf16(h18, h19);
            alo[mt][kt][0] = pack_bf16(
                __float2bfloat16(w00 - __bfloat162float(h00)),
                __float2bfloat16(w01 - __bfloat162float(h01)));
            alo[mt][kt][1] = pack_bf16(
                __float2bfloat16(w10 - __bfloat162float(h10)),
                __float2bfloat16(w11 - __bfloat162float(h11)));
            alo[mt][kt][2] = pack_bf16(
                __float2bfloat16(w08 - __bfloat162float(h08)),
                __float2bfloat16(w09 - __bfloat162float(h09)));
            alo[mt][kt][3] = pack_bf16(
                __float2bfloat16(w18 - __bfloat162float(h18)),
                __float2bfloat16(w19 - __bfloat162float(h19)));
        }
    }

    // zero h buffers (hi/lo, both parities; rows 4-7 stay zero forever)
    for (int idx = tid; idx < L_SMEM_B/4; idx += 512)
        ((unsigned*)smc)[idx] = 0u;
    __syncthreads();

    // ldmatrix B lane offset: lanes 0-7 rows (batch), 8-15 rows (col+8)
    const unsigned b_lane = (unsigned)((lane & 7) * HB_ROW_B + ((lane >> 3) & 1) * 16);

    // h write byte offsets (batch rows qc, qc+1; column jglob)
    const unsigned hwo0 = (unsigned)(qc)     * HB_ROW_B + (unsigned)jglob * 2;
    const unsigned hwo1 = (unsigned)(qc + 1) * HB_ROW_B + (unsigned)jglob * 2;

    float creg[2] = {0.f, 0.f};
    int p = 0;

    const size_t gx_stride_t = (size_t)Bq * G4q;
    // guard invalid lanes against OOB batch index
    const int bglob = cl * 4 + (valid ? qc : 0);
    const float* gx_b = g_gx + (size_t)bglob * G4q + jglob;

    // prefetch gx for t=0
    float gxr[2][4];
    if (valid) {
        #pragma unroll
        for (int g = 0; g < 4; g++) {
            gxr[0][g] = __ldg(gx_b + g * Hq);
            gxr[1][g] = __ldg(gx_b + G4q + g * Hq);
        }
    }

    for (int t = 0; t < Tq; t++) {
        // ---- GEMM: 3 independent accumulator chains per m-tile ----
        float cA0[4] = {0,0,0,0}, cB0[4] = {0,0,0,0}, cC0[4] = {0,0,0,0};
        float cA1[4] = {0,0,0,0}, cB1[4] = {0,0,0,0}, cC1[4] = {0,0,0,0};
        const unsigned bhi_base = sbase + HB_HI(p) + b_lane;
        const unsigned blo_base = sbase + HB_LO(p) + b_lane;

        #pragma unroll
        for (int kt = 0; kt < 8; kt++) {
            unsigned bh0, bh1, bl0r, bl1r;
            ldsm_x2(bh0, bh1, bhi_base + kt * 32);
            ldsm_x2(bl0r, bl1r, blo_base + kt * 32);
            mma_bf16(cA0, ahi[0][kt], bh0, bh1);
            mma_bf16(cB0, ahi[0][kt], bl0r, bl1r);
            mma_bf16(cC0, alo[0][kt], bh0, bh1);
            mma_bf16(cA1, ahi[1][kt], bh0, bh1);
            mma_bf16(cB1, ahi[1][kt], bl0r, bl1r);
            mma_bf16(cC1, alo[1][kt], bh0, bh1);
        }

        const int pw = p ^ 1;
        if (valid) {
            // sums: s0[0..1]=gate0(i) b=qc,qc+1; s0[2..3]=gate1(f);
            //       s1[0..1]=gate2(g); s1[2..3]=gate3(o)
            float s0[4], s1[4];
            #pragma unroll
            for (int j = 0; j < 4; j++) {
                s0[j] = cA0[j] + cB0[j] + cC0[j];
                s1[j] = cA1[j] + cB1[j] + cC1[j];
            }

            #pragma unroll
            for (int bb = 0; bb < 2; bb++) {
                float vi = s0[bb]     + gxr[bb][0];
                float vf = s0[2 + bb] + gxr[bb][1];
                float vg = s1[bb]     + gxr[bb][2];
                float vo = s1[2 + bb] + gxr[bb][3];
                float si = sig_hw(vi);
                float sf = sig_hw(vf);
                float so = sig_hw(vo);
                float tg = tanh_hw(vg);
                float cn = sf * creg[bb] + si * tg;
                creg[bb] = cn;
                float hn = so * tanh_hw(cn);

                __nv_bfloat16 hh = __float2bfloat16(hn);
                __nv_bfloat16 hl = __float2bfloat16(hn - __bfloat162float(hh));
                unsigned short hhb = __bfloat16_as_ushort(hh);
                unsigned short hlb = __bfloat16_as_ushort(hl);
                unsigned off = (bb == 0) ? hwo0 : hwo1;
                asm volatile("st.shared.u16 [%0], %1;"
                             :: "r"(sbase + HB_HI(pw) + off), "h"(hhb) : "memory");
                asm volatile("st.shared.u16 [%0], %1;"
                             :: "r"(sbase + HB_LO(pw) + off), "h"(hlb) : "memory");
                if (t == Tq - 1)
                    g_hfin[(size_t)(cl * 4 + qc + bb) * Hq + jglob] = hn;
            }

            // prefetch gx for t+1
            if (t + 1 < Tq) {
                const float* gxp = gx_b + (size_t)(t + 1) * gx_stride_t;
                #pragma unroll
                for (int g = 0; g < 4; g++) {
                    gxr[0][g] = __ldg(gxp + g * Hq);
                    gxr[1][g] = __ldg(gxp + G4q + g * Hq);
                }
            }
        }

        // ---- step sync ----
        __syncthreads();
        p ^= 1;
    }
}

// ---------------------------------------------------------------------------
// Classifier: out = h_final @ Wc^T + bc, [512 x 21], K=128
// ---------------------------------------------------------------------------
__global__ void cls_kernel(const float* __restrict__ Wc,
                           const float* __restrict__ bc,
                           float* __restrict__ out)
{
    int gid = blockIdx.x * blockDim.x + threadIdx.x;
    if (gid >= Bq * 21) return;
    int b = gid / 21, c = gid % 21;
    const float* h = g_hfin + b * Hq;
    const float* w = Wc + c * Hq;
    float s = 0.f;
    #pragma unroll 8
    for (int k = 0; k < Hq; k++) s += h[k] * w[k];
    out[gid] = s + bc[c];
}

// ---------------------------------------------------------------------------
extern "C" void kernel_launch(void* const* d_in, const int* in_sizes, int n_in,
                              void* d_out, int out_size)
{
    (void)in_sizes; (void)n_in; (void)out_size;
    const float* x   = (const float*)d_in[0];
    const float* W1  = (const float*)d_in[1];
    const float* b1  = (const float*)d_in[2];
    const float* W2  = (const float*)d_in[3];
    const float* b2  = (const float*)d_in[4];
    const float* Wih = (const float*)d_in[5];
    const float* Whh = (const float*)d_in[6];
    const float* bih = (const float*)d_in[7];
    const float* bhh = (const float*)d_in[8];
    const float* Wc  = (const float*)d_in[9];
    const float* bc  = (const float*)d_in[10];
    float* out = (float*)d_out;

    cudaFuncSetAttribute(enc_hmma_kernel, cudaFuncAttributeMaxDynamicSharedMemorySize,
                         E_TOTAL);
    cudaFuncSetAttribute(lstm_persist_kernel, cudaFuncAttributeMaxDynamicSharedMemorySize,
                         L_SMEM_B);

    prep_kernel<<<(G4q*Eq + 255)/256, 256>>>(Wih, bih, bhh, W1, W2);

    enc_hmma_kernel<<<NROWS/64, 256, E_TOTAL>>>(x, b1, b2);

    gx_hmma_kernel<<<dim3(NROWS/64, 8), 256>>>();

    lstm_persist_kernel<<<128, 512, L_SMEM_B>>>(Whh);

    cls_kernel<<<(Bq*21 + 255)/256, 256>>>(Wc, bc, out);
}

// round 17
// speedup vs baseline: 1.4591x; 1.4591x over previous
#include <cuda_runtime.h>
#include <cuda_bf16.h>
#include <stdint.h>
#include <math.h>

#define Bq 512
#define Tq 512
#define Fq 52
#define Eq 64
#define Hq 128
#define G4q 512
#define NROWS (Bq*Tq)

// Scratch (device globals; no dynamic allocation allowed)
__device__ __nv_bfloat16 g_henc_h[NROWS * Eq];   // 32 MB  h_enc hi
__device__ __nv_bfloat16 g_henc_l[NROWS * Eq];   // 32 MB  h_enc lo
__device__ __nv_bfloat16 g_wih_h[G4q * Eq];      // W_ih hi
__device__ __nv_bfloat16 g_wih_l[G4q * Eq];      // W_ih lo
__device__ __nv_bfloat16 g_w1h[128 * 64];        // W1 hi (K padded to 64)
__device__ __nv_bfloat16 g_w1l[128 * 64];        // W1 lo
__device__ __nv_bfloat16 g_w2h[64 * 128];        // W2 hi
__device__ __nv_bfloat16 g_w2l[64 * 128];        // W2 lo
__device__ float g_bias[G4q];                    // b_ih + b_hh
__device__ float g_gx[NROWS * G4q];              // 512 MB [t][b][512]
__device__ float g_hfin[Bq * Hq];                // final hidden state

// ---------------------------------------------------------------------------
// helpers
// ---------------------------------------------------------------------------
__device__ __forceinline__ unsigned smem_u32(const void* p) {
    unsigned a;
    asm("{ .reg .u64 t; cvta.to.shared.u64 t, %1; cvt.u32.u64 %0, t; }"
        : "=r"(a) : "l"(p));
    return a;
}

__device__ __forceinline__ float sigf(float x) {
    return __fdividef(1.f, 1.f + __expf(-x));
}
__device__ __forceinline__ float tanhf_s(float x) {
    float ax = fabsf(x);
    float e  = __expf(-2.f * ax);            // in (0,1], never overflows
    float r  = __fdividef(1.f - e, 1.f + e);
    return copysignf(r, x);
}

// pack two bf16 (e0 -> low half, e1 -> high half)
__device__ __forceinline__ unsigned pack_bf16(__nv_bfloat16 e0, __nv_bfloat16 e1) {
    return ((unsigned)__bfloat16_as_ushort(e1) << 16) |
           (unsigned)__bfloat16_as_ushort(e0);
}

// m16n8k16 row.col f32.bf16.bf16.f32 (baseline PTX, sm_80+)
__device__ __forceinline__ void mma_bf16(float c[4], const unsigned a[4],
                                         unsigned b0, unsigned b1) {
    asm volatile(
        "mma.sync.aligned.m16n8k16.row.col.f32.bf16.bf16.f32 "
        "{%0,%1,%2,%3}, {%4,%5,%6,%7}, {%8,%9}, {%0,%1,%2,%3};"
        : "+f"(c[0]), "+f"(c[1]), "+f"(c[2]), "+f"(c[3])
        : "r"(a[0]), "r"(a[1]), "r"(a[2]), "r"(a[3]), "r"(b0), "r"(b1));
}

// ldmatrix wrappers (baseline PTX, sm_75+)
__device__ __forceinline__ void ldsm_x4(unsigned r[4], unsigned addr) {
    asm volatile("ldmatrix.sync.aligned.m8n8.x4.shared.b16 {%0,%1,%2,%3}, [%4];"
        : "=r"(r[0]), "=r"(r[1]), "=r"(r[2]), "=r"(r[3]) : "r"(addr));
}
__device__ __forceinline__ void ldsm_x2(unsigned& r0, unsigned& r1, unsigned addr) {
    asm volatile("ldmatrix.sync.aligned.m8n8.x2.shared.b16 {%0,%1}, [%2];"
        : "=r"(r0), "=r"(r1) : "r"(addr));
}

// ---------------------------------------------------------------------------
// prep: split W_ih / W1 / W2 to bf16 hi/lo; bias = b_ih + b_hh
// ---------------------------------------------------------------------------
__global__ void prep_kernel(const float* __restrict__ Wih,
                            const float* __restrict__ bih,
                            const float* __restrict__ bhh,
                            const float* __restrict__ W1,
                            const float* __restrict__ W2)
{
    int i = blockIdx.x * 256 + threadIdx.x;
    if (i < G4q * Eq) {
        float v = Wih[i];
        __nv_bfloat16 h = __float2bfloat16(v);
        g_wih_h[i] = h;
        g_wih_l[i] = __float2bfloat16(v - __bfloat162float(h));
    }
    if (i < 128 * 64) {
        int r = i >> 6, k = i & 63;
        float v = (k < Fq) ? W1[r * Fq + k] : 0.f;
        __nv_bfloat16 h = __float2bfloat16(v);
        g_w1h[i] = h;
        g_w1l[i] = __float2bfloat16(v - __bfloat162float(h));
    }
    if (i < 64 * 128) {
        float v = W2[i];
        __nv_bfloat16 h = __float2bfloat16(v);
        g_w2h[i] = h;
        g_w2l[i] = __float2bfloat16(v - __bfloat162float(h));
    }
    if (i < G4q) g_bias[i] = bih[i] + bhh[i];
}

// ---------------------------------------------------------------------------
// Fused HMMA encoder (unchanged from R11)
// ---------------------------------------------------------------------------
#define E_W2H 0
#define E_W2L 17408
#define E_R   34816
#define E_AXH E_R
#define E_AXL (E_R + 9216)
#define E_W1H (E_R + 18432)
#define E_W1L (E_R + 36864)
#define E_H1H E_R
#define E_H1L (E_R + 17408)
#define E_B1  (E_R + 55296)
#define E_B2  (E_B1 + 512)
#define E_TOTAL (E_B2 + 256)

__global__ __launch_bounds__(256) void enc_hmma_kernel(
    const float* __restrict__ x,
    const float* __restrict__ b1, const float* __restrict__ b2)
{
    extern __shared__ char smc[];
    __nv_bfloat16* W2h = (__nv_bfloat16*)(smc + E_W2H);
    __nv_bfloat16* W2l = (__nv_bfloat16*)(smc + E_W2L);
    __nv_bfloat16* Axh = (__nv_bfloat16*)(smc + E_AXH);
    __nv_bfloat16* Axl = (__nv_bfloat16*)(smc + E_AXL);
    __nv_bfloat16* W1h = (__nv_bfloat16*)(smc + E_W1H);
    __nv_bfloat16* W1l = (__nv_bfloat16*)(smc + E_W1L);
    __nv_bfloat16* H1h = (__nv_bfloat16*)(smc + E_H1H);
    __nv_bfloat16* H1l = (__nv_bfloat16*)(smc + E_H1L);
    float* b1s = (float*)(smc + E_B1);
    float* b2s = (float*)(smc + E_B2);

    const int tid  = threadIdx.x;
    const int w    = tid >> 5;
    const int lane = tid & 31;
    const int qr   = lane >> 2;
    const int qc   = (lane & 3) * 2;
    const int row0 = blockIdx.x * 64;

    for (int idx = tid; idx < 64 * 32; idx += 256) {
        int r = idx >> 5, c4 = (idx & 31) * 4;
        *(uint2*)&W2h[r * 136 + c4] = *(const uint2*)(g_w2h + r * 128 + c4);
        *(uint2*)&W2l[r * 136 + c4] = *(const uint2*)(g_w2l + r * 128 + c4);
    }
    for (int idx = tid; idx < 128 * 16; idx += 256) {
        int r = idx >> 4, c4 = (idx & 15) * 4;
        *(uint2*)&W1h[r * 72 + c4] = *(const uint2*)(g_w1h + r * 64 + c4);
        *(uint2*)&W1l[r * 72 + c4] = *(const uint2*)(g_w1l + r * 64 + c4);
    }
    for (int idx = tid; idx < 64 * Fq; idx += 256) {
        int r = idx / Fq, k = idx % Fq;
        float v = x[(size_t)(row0 + r) * Fq + k];
        __nv_bfloat16 h = __float2bfloat16(v);
        Axh[r * 72 + k] = h;
        Axl[r * 72 + k] = __float2bfloat16(v - __bfloat162float(h));
    }
    for (int idx = tid; idx < 64 * 12; idx += 256) {
        int r = idx / 12, k = Fq + idx % 12;
        Axh[r * 72 + k] = __float2bfloat16(0.f);
        Axl[r * 72 + k] = __float2bfloat16(0.f);
    }
    if (tid < 128) b1s[tid] = b1[tid];
    if (tid < 64)  b2s[tid] = b2[tid];
    __syncthreads();

    // phase 1
    float cH[4][2][4], cX[4][2][4];
    #pragma unroll
    for (int mt = 0; mt < 4; mt++)
        #pragma unroll
        for (int nb = 0; nb < 2; nb++)
            #pragma unroll
            for (int j = 0; j < 4; j++) { cH[mt][nb][j] = 0.f; cX[mt][nb][j] = 0.f; }

    #pragma unroll
    for (int kt = 0; kt < 4; kt++) {
        int bk = kt * 16 + qc;
        unsigned bh[2][2], bl[2][2];
        #pragma unroll
        for (int nb = 0; nb < 2; nb++) {
            int nrow = (w * 2 + nb) * 8 + qr;
            bh[nb][0] = *(const unsigned*)&W1h[nrow * 72 + bk];
            bh[nb][1] = *(const unsigned*)&W1h[nrow * 72 + bk + 8];
            bl[nb][0] = *(const unsigned*)&W1l[nrow * 72 + bk];
            bl[nb][1] = *(const unsigned*)&W1l[nrow * 72 + bk + 8];
        }
        #pragma unroll
        for (int mt = 0; mt < 4; mt++) {
            int ar = mt * 16 + qr;
            unsigned a_h[4] = {
                *(const unsigned*)&Axh[ar * 72 + bk],
                *(const unsigned*)&Axh[(ar + 8) * 72 + bk],
                *(const unsigned*)&Axh[ar * 72 + bk + 8],
                *(const unsigned*)&Axh[(ar + 8) * 72 + bk + 8] };
            unsigned a_l[4] = {
                *(const unsigned*)&Axl[ar * 72 + bk],
                *(const unsigned*)&Axl[(ar + 8) * 72 + bk],
                *(const unsigned*)&Axl[ar * 72 + bk + 8],
                *(const unsigned*)&Axl[(ar + 8) * 72 + bk + 8] };
            #pragma unroll
            for (int nb = 0; nb < 2; nb++) {
                mma_bf16(cH[mt][nb], a_h, bh[nb][0], bh[nb][1]);
                mma_bf16(cX[mt][nb], a_h, bl[nb][0], bl[nb][1]);
                mma_bf16(cX[mt][nb], a_l, bh[nb][0], bh[nb][1]);
            }
        }
    }
    __syncthreads();

    #pragma unroll
    for (int mt = 0; mt < 4; mt++) {
        #pragma unroll
        for (int nb = 0; nb < 2; nb++) {
            int ncol = (w * 2 + nb) * 8 + qc;
            float bv0 = b1s[ncol], bv1 = b1s[ncol + 1];
            #pragma unroll
            for (int half = 0; half < 2; half++) {
                int r = mt * 16 + qr + half * 8;
                float v0 = cH[mt][nb][half*2]   + cX[mt][nb][half*2]   + bv0;
                float v1 = cH[mt][nb][half*2+1] + cX[mt][nb][half*2+1] + bv1;
                v0 = v0 > 0.f ? v0 : 0.f;
                v1 = v1 > 0.f ? v1 : 0.f;
                __nv_bfloat16 h0 = __float2bfloat16(v0);
                __nv_bfloat16 h1 = __float2bfloat16(v1);
                *(unsigned*)&H1h[r * 136 + ncol] = pack_bf16(h0, h1);
                *(unsigned*)&H1l[r * 136 + ncol] = pack_bf16(
                    __float2bfloat16(v0 - __bfloat162float(h0)),
                    __float2bfloat16(v1 - __bfloat162float(h1)));
            }
        }
    }
    __syncthreads();

    // phase 2
    float dH[4][4], dX[4][4];
    #pragma unroll
    for (int mt = 0; mt < 4; mt++)
        #pragma unroll
        for (int j = 0; j < 4; j++) { dH[mt][j] = 0.f; dX[mt][j] = 0.f; }

    #pragma unroll
    for (int kt = 0; kt < 8; kt++) {
        int bk = kt * 16 + qc;
        int nrow = w * 8 + qr;
        unsigned bh0 = *(const unsigned*)&W2h[nrow * 136 + bk];
        unsigned bh1 = *(const unsigned*)&W2h[nrow * 136 + bk + 8];
        unsigned bl0 = *(const unsigned*)&W2l[nrow * 136 + bk];
        unsigned bl1 = *(const unsigned*)&W2l[nrow * 136 + bk + 8];
        #pragma unroll
        for (int mt = 0; mt < 4; mt++) {
            int ar = mt * 16 + qr;
            unsigned a_h[4] = {
                *(const unsigned*)&H1h[ar * 136 + bk],
                *(const unsigned*)&H1h[(ar + 8) * 136 + bk],
                *(const unsigned*)&H1h[ar * 136 + bk + 8],
                *(const unsigned*)&H1h[(ar + 8) * 136 + bk + 8] };
            unsigned a_l[4] = {
                *(const unsigned*)&H1l[ar * 136 + bk],
                *(const unsigned*)&H1l[(ar + 8) * 136 + bk],
                *(const unsigned*)&H1l[ar * 136 + bk + 8],
                *(const unsigned*)&H1l[(ar + 8) * 136 + bk + 8] };
            mma_bf16(dH[mt], a_h, bh0, bh1);
            mma_bf16(dX[mt], a_h, bl0, bl1);
            mma_bf16(dX[mt], a_l, bh0, bh1);
        }
    }

    {
        int ncol = w * 8 + qc;
        float bv0 = b2s[ncol], bv1 = b2s[ncol + 1];
        #pragma unroll
        for (int mt = 0; mt < 4; mt++) {
            #pragma unroll
            for (int half = 0; half < 2; half++) {
                int r = row0 + mt * 16 + qr + half * 8;
                float v0 = dH[mt][half*2]   + dX[mt][half*2]   + bv0;
                float v1 = dH[mt][half*2+1] + dX[mt][half*2+1] + bv1;
                v0 = v0 > 0.f ? v0 : 0.f;
                v1 = v1 > 0.f ? v1 : 0.f;
                __nv_bfloat16 h0 = __float2bfloat16(v0);
                __nv_bfloat16 h1 = __float2bfloat16(v1);
                *(unsigned*)(g_henc_h + (size_t)r * Eq + ncol) = pack_bf16(h0, h1);
                *(unsigned*)(g_henc_l + (size_t)r * Eq + ncol) = pack_bf16(
                    __float2bfloat16(v0 - __bfloat162float(h0)),
                    __float2bfloat16(v1 - __bfloat162float(h1)));
            }
        }
    }
}

// ---------------------------------------------------------------------------
// gx via HMMA bf16 2-way split, fragments loaded with ldmatrix. (R14)
// ---------------------------------------------------------------------------
#define GX_RSTRIDE_B 144

__global__ __launch_bounds__(256) void gx_hmma_kernel()
{
    __shared__ __nv_bfloat16 Ah[64][72], Al[64][72];
    __shared__ __nv_bfloat16 Bh[64][72], Bl[64][72];
    __shared__ float bs[64];

    const int tid  = threadIdx.x;
    const int w    = tid >> 5;
    const int lane = tid & 31;
    const int row0 = blockIdx.x * 64;
    const int cb   = blockIdx.y * 64;

    for (int idx = tid; idx < 64 * 16; idx += 256) {
        int r  = idx >> 4;
        int k4 = (idx & 15) * 4;
        size_t ga = (size_t)(row0 + r) * Eq + k4;
        size_t gb = (size_t)(cb + r) * Eq + k4;
        *(uint2*)&Ah[r][k4] = *(const uint2*)(g_henc_h + ga);
        *(uint2*)&Al[r][k4] = *(const uint2*)(g_henc_l + ga);
        *(uint2*)&Bh[r][k4] = *(const uint2*)(g_wih_h + gb);
        *(uint2*)&Bl[r][k4] = *(const uint2*)(g_wih_l + gb);
    }
    if (tid < 64) bs[tid] = g_bias[cb + tid];
    __syncthreads();

    const int qr = lane >> 2;
    const int qc = (lane & 3) * 2;

    const unsigned a_lane = (unsigned)((((lane >> 3) & 1) * 8 + (lane & 7)) * GX_RSTRIDE_B
                                       + (lane >> 4) * 16);
    const unsigned b_lane = (unsigned)((lane & 7) * GX_RSTRIDE_B + ((lane >> 3) & 1) * 16);

    const unsigned uAh = smem_u32(Ah), uAl = smem_u32(Al);
    const unsigned uBh = smem_u32(Bh) + (unsigned)(w * 8 * GX_RSTRIDE_B);
    const unsigned uBl = smem_u32(Bl) + (unsigned)(w * 8 * GX_RSTRIDE_B);

    float cA[4][4], cB[4][4], cC[4][4];
    #pragma unroll
    for (int m = 0; m < 4; m++)
        #pragma unroll
        for (int j = 0; j < 4; j++) { cA[m][j] = 0.f; cB[m][j] = 0.f; cC[m][j] = 0.f; }

    #pragma unroll
    for (int kt = 0; kt < 4; kt++) {
        unsigned bh0, bh1, bl0, bl1;
        ldsm_x2(bh0, bh1, uBh + b_lane + kt * 32);
        ldsm_x2(bl0, bl1, uBl + b_lane + kt * 32);
        #pragma unroll
        for (int mt = 0; mt < 4; mt++) {
            unsigned a_h[4], a_l[4];
            ldsm_x4(a_h, uAh + (unsigned)(mt * 16 * GX_RSTRIDE_B) + a_lane + kt * 32);
            ldsm_x4(a_l, uAl + (unsigned)(mt * 16 * GX_RSTRIDE_B) + a_lane + kt * 32);
            mma_bf16(cA[mt], a_h, bh0, bh1);
            mma_bf16(cB[mt], a_h, bl0, bl1);
            mma_bf16(cC[mt], a_l, bh0, bh1);
        }
    }

    const int ncol = cb + w*8 + qc;
    const float bv0 = bs[w*8 + qc];
    const float bv1 = bs[w*8 + qc + 1];
    #pragma unroll
    for (int mt = 0; mt < 4; mt++) {
        int r1 = row0 + mt*16 + qr;
        int r2 = r1 + 8;
        int b1i = r1 >> 9, t1 = r1 & 511;
        int b2i = r2 >> 9, t2 = r2 & 511;
        float2 o1 = make_float2(cA[mt][0] + cB[mt][0] + cC[mt][0] + bv0,
                                cA[mt][1] + cB[mt][1] + cC[mt][1] + bv1);
        float2 o2 = make_float2(cA[mt][2] + cB[mt][2] + cC[mt][2] + bv0,
                                cA[mt][3] + cB[mt][3] + cC[mt][3] + bv1);
        *(float2*)(g_gx + ((size_t)t1 * Bq + b1i) * G4q + ncol) = o1;
        *(float2*)(g_gx + ((size_t)t2 * Bq + b2i) * G4q + ncol) = o2;
    }
}

// ---------------------------------------------------------------------------
// Persistent LSTM (R14 structure): gate-remapped A fragments, register
// epilogue, barrier.cluster step sync, ldmatrix B loads. Single change:
// the two correction chains (whi*hlo, wlo*hhi) share ONE accumulator set
// (cX, chain depth 2) to cut 8 registers of pressure.
// ---------------------------------------------------------------------------
#define HB_ROW_BF16 152
#define HB_ROW_B    (HB_ROW_BF16*2)       // 304
#define HB_ARR_B    (8*HB_ROW_B)          // 2432
#define HB_HI(p)    ((p)*2*HB_ARR_B)
#define HB_LO(p)    ((p)*2*HB_ARR_B + HB_ARR_B)
#define L_SMEM_B    (4*HB_ARR_B)

__global__ __launch_bounds__(256, 1) __cluster_dims__(2, 1, 1)
void lstm_persist_kernel(const float* __restrict__ Whh)
{
    extern __shared__ char smc[];
    const unsigned sbase = smem_u32(smc);

    const int tid  = threadIdx.x;
    const int w    = tid >> 5;
    const int lane = tid & 31;
    const int qr   = lane >> 2;
    const int qc   = (lane & 3) << 1;
    unsigned rank;
    asm("mov.u32 %0, %%cluster_ctarank;" : "=r"(rank));
    const int cl = blockIdx.x >> 1;
    const int j0 = (int)rank * 64;
    const int jglob = j0 + w * 8 + qr;

    // ---- A fragments: all 4 gates of column jglob ----
    unsigned ahi[2][8][4], alo[2][8][4];
    #pragma unroll
    for (int mt = 0; mt < 2; mt++) {
        long r0 = (long)((mt*2 + 0) * Hq + jglob) * Hq;   // even gate row
        long r1 = (long)((mt*2 + 1) * Hq + jglob) * Hq;   // odd gate row
        #pragma unroll
        for (int kt = 0; kt < 8; kt++) {
            int c0 = kt*16 + qc;
            float w00 = Whh[r0 + c0],     w01 = Whh[r0 + c0 + 1];
            float w08 = Whh[r0 + c0 + 8], w09 = Whh[r0 + c0 + 9];
            float w10 = Whh[r1 + c0],     w11 = Whh[r1 + c0 + 1];
            float w18 = Whh[r1 + c0 + 8], w19 = Whh[r1 + c0 + 9];
            __nv_bfloat16 h00 = __float2bfloat16(w00), h01 = __float2bfloat16(w01);
            __nv_bfloat16 h08 = __float2bfloat16(w08), h09 = __float2bfloat16(w09);
            __nv_bfloat16 h10 = __float2bfloat16(w10), h11 = __float2bfloat16(w11);
            __nv_bfloat16 h18 = __float2bfloat16(w18), h19 = __float2bfloat16(w19);
            ahi[mt][kt][0] = pack_bf16(h00, h01);
            ahi[mt][kt][1] = pack_bf16(h10, h11);
            ahi[mt][kt][2] = pack_bf16(h08, h09);
            ahi[mt][kt][3] = pack_bf16(h18, h19);
            alo[mt][kt][0] = pack_bf16(
                __float2bfloat16(w00 - __bfloat162float(h00)),
                __float2bfloat16(w01 - __bfloat162float(h01)));
            alo[mt][kt][1] = pack_bf16(
                __float2bfloat16(w10 - __bfloat162float(h10)),
                __float2bfloat16(w11 - __bfloat162float(h11)));
            alo[mt][kt][2] = pack_bf16(
                __float2bfloat16(w08 - __bfloat162float(h08)),
                __float2bfloat16(w09 - __bfloat162float(h09)));
            alo[mt][kt][3] = pack_bf16(
                __float2bfloat16(w18 - __bfloat162float(h18)),
                __float2bfloat16(w19 - __bfloat162float(h19)));
        }
    }

    // zero h buffers (hi/lo, both parities)
    for (int idx = tid; idx < L_SMEM_B/4; idx += 256)
        ((unsigned*)smc)[idx] = 0u;
    __syncthreads();
    asm volatile("barrier.cluster.arrive.aligned;" ::: "memory");
    asm volatile("barrier.cluster.wait.aligned;" ::: "memory");

    unsigned peer_base;
    asm("mapa.shared::cluster.u32 %0, %1, %2;"
        : "=r"(peer_base) : "r"(sbase), "r"(rank ^ 1u));

    // ldmatrix B lane offset: lanes 0-7 rows, 8-15 rows (col+8)
    const unsigned b_lane = (unsigned)((lane & 7) * HB_ROW_B + ((lane >> 3) & 1) * 16);

    // h write byte offsets (batches qc, qc+1 at col jglob)
    const unsigned hwo0 = (unsigned)(qc)     * HB_ROW_B + (unsigned)jglob * 2;
    const unsigned hwo1 = (unsigned)(qc + 1) * HB_ROW_B + (unsigned)jglob * 2;

    float creg[2] = {0.f, 0.f};
    int p = 0;

    const size_t gx_stride_t = (size_t)Bq * G4q;
    const float* gx_b = g_gx + (size_t)(cl * 8 + qc) * G4q + jglob;

    // prefetch gx for t=0
    float gxr[2][4];
    #pragma unroll
    for (int g = 0; g < 4; g++) {
        gxr[0][g] = __ldg(gx_b + g * Hq);
        gxr[1][g] = __ldg(gx_b + G4q + g * Hq);
    }

    for (int t = 0; t < Tq; t++) {
        // ---- GEMM: main chain cA*, correction chain cX* (depth 2/kt) ----
        float cA0[4] = {0,0,0,0}, cX0[4] = {0,0,0,0};
        float cA1[4] = {0,0,0,0}, cX1[4] = {0,0,0,0};
        const unsigned bhi_base = sbase + HB_HI(p) + b_lane;
        const unsigned blo_base = sbase + HB_LO(p) + b_lane;

        #pragma unroll
        for (int kt = 0; kt < 8; kt++) {
            unsigned bh0, bh1, bl0r, bl1r;
            ldsm_x2(bh0, bh1, bhi_base + kt * 32);
            ldsm_x2(bl0r, bl1r, blo_base + kt * 32);
            mma_bf16(cA0, ahi[0][kt], bh0, bh1);
            mma_bf16(cX0, ahi[0][kt], bl0r, bl1r);
            mma_bf16(cX0, alo[0][kt], bh0, bh1);
            mma_bf16(cA1, ahi[1][kt], bh0, bh1);
            mma_bf16(cX1, ahi[1][kt], bl0r, bl1r);
            mma_bf16(cX1, alo[1][kt], bh0, bh1);
        }

        // sums: s0[0..1]=gate0(i) b=qc,qc+1; s0[2..3]=gate1(f);
        //       s1[0..1]=gate2(g); s1[2..3]=gate3(o)
        float s0[4], s1[4];
        #pragma unroll
        for (int j = 0; j < 4; j++) {
            s0[j] = cA0[j] + cX0[j];
            s1[j] = cA1[j] + cX1[j];
        }

        // ---- epilogue straight out of registers ----
        const int pw = p ^ 1;
        #pragma unroll
        for (int bb = 0; bb < 2; bb++) {
            float vi = s0[bb]     + gxr[bb][0];
            float vf = s0[2 + bb] + gxr[bb][1];
            float vg = s1[bb]     + gxr[bb][2];
            float vo = s1[2 + bb] + gxr[bb][3];
            float si = sigf(vi);
            float sf = sigf(vf);
            float so = sigf(vo);
            float tg = tanhf_s(vg);
            float cn = sf * creg[bb] + si * tg;
            creg[bb] = cn;
            float hn = so * tanhf_s(cn);

            __nv_bfloat16 hh = __float2bfloat16(hn);
            __nv_bfloat16 hl = __float2bfloat16(hn - __bfloat162float(hh));
            unsigned short hhb = __bfloat16_as_ushort(hh);
            unsigned short hlb = __bfloat16_as_ushort(hl);
            unsigned off = (bb == 0) ? hwo0 : hwo1;
            asm volatile("st.shared.u16 [%0], %1;"
                         :: "r"(sbase + HB_HI(pw) + off), "h"(hhb) : "memory");
            asm volatile("st.shared.u16 [%0], %1;"
                         :: "r"(sbase + HB_LO(pw) + off), "h"(hlb) : "memory");
            asm volatile("st.shared::cluster.u16 [%0], %1;"
                         :: "r"(peer_base + HB_HI(pw) + off), "h"(hhb) : "memory");
            asm volatile("st.shared::cluster.u16 [%0], %1;"
                         :: "r"(peer_base + HB_LO(pw) + off), "h"(hlb) : "memory");
            if (t == Tq - 1)
                g_hfin[(size_t)(cl * 8 + qc + bb) * Hq + jglob] = hn;
        }

        // ---- prefetch gx for t+1 ----
        if (t + 1 < Tq) {
            const float* gxp = gx_b + (size_t)(t + 1) * gx_stride_t;
            #pragma unroll
            for (int g = 0; g < 4; g++) {
                gxr[0][g] = __ldg(gxp + g * Hq);
                gxr[1][g] = __ldg(gxp + G4q + g * Hq);
            }
        }

        // ---- step sync: barrier.cluster (orders DSMEM h writes) ----
        asm volatile("barrier.cluster.arrive.aligned;" ::: "memory");
        asm volatile("barrier.cluster.wait.aligned;" ::: "memory");
        p ^= 1;
    }
}

// ---------------------------------------------------------------------------
// Classifier: out = h_final @ Wc^T + bc, [512 x 21], K=128
// ---------------------------------------------------------------------------
__global__ void cls_kernel(const float* __restrict__ Wc,
                           const float* __restrict__ bc,
                           float* __restrict__ out)
{
    int gid = blockIdx.x * blockDim.x + threadIdx.x;
    if (gid >= Bq * 21) return;
    int b = gid / 21, c = gid % 21;
    const float* h = g_hfin + b * Hq;
    const float* w = Wc + c * Hq;
    float s = 0.f;
    #pragma unroll 8
    for (int k = 0; k < Hq; k++) s += h[k] * w[k];
    out[gid] = s + bc[c];
}

// ---------------------------------------------------------------------------
extern "C" void kernel_launch(void* const* d_in, const int* in_sizes, int n_in,
                              void* d_out, int out_size)
{
    (void)in_sizes; (void)n_in; (void)out_size;
    const float* x   = (const float*)d_in[0];
    const float* W1  = (const float*)d_in[1];
    const float* b1  = (const float*)d_in[2];
    const float* W2  = (const float*)d_in[3];
    const float* b2  = (const float*)d_in[4];
    const float* Wih = (const float*)d_in[5];
    const float* Whh = (const float*)d_in[6];
    const float* bih = (const float*)d_in[7];
    const float* bhh = (const float*)d_in[8];
    const float* Wc  = (const float*)d_in[9];
    const float* bc  = (const float*)d_in[10];
    float* out = (float*)d_out;

    cudaFuncSetAttribute(enc_hmma_kernel, cudaFuncAttributeMaxDynamicSharedMemorySize,
                         E_TOTAL);
    cudaFuncSetAttribute(lstm_persist_kernel, cudaFuncAttributeMaxDynamicSharedMemorySize,
                         L_SMEM_B);

    prep_kernel<<<(G4q*Eq + 255)/256, 256>>>(Wih, bih, bhh, W1, W2);

    enc_hmma_kernel<<<NROWS/64, 256, E_TOTAL>>>(x, b1, b2);

    gx_hmma_kernel<<<dim3(NROWS/64, 8), 256>>>();

    lstm_persist_kernel<<<128, 256, L_SMEM_B>>>(Whh);

    cls_kernel<<<(Bq*21 + 255)/256, 256>>>(Wc, bc, out);
}